// round 7
// baseline (speedup 1.0000x reference)
#include <cuda_runtime.h>
#include <math.h>
#include <stdint.h>

// Problem constants
#define Bq   4
#define Tq   2048
#define Eq   1024
#define Hq   16
#define Dq   64
#define BHq  (Bq*Hq)

typedef unsigned long long ull;

// Scratch (alloc-free rule: static __device__ arrays). 32 MB each.
__device__ float g_Q [(size_t)BHq * Tq * Dq];   // pre-scaled by 0.125*log2(e)
__device__ float g_K [(size_t)BHq * Tq * Dq];   // d-columns pair-permuted
__device__ float g_V [(size_t)BHq * Tq * Dq];   // row-major (residual/epilogue)
__device__ float g_Vt[(size_t)BHq * Dq * Tq];   // transposed (identity order)

#define SCALE_LOG2E 0.18033688011112042f   // 0.125 * log2(e)

// ---- packed f32x2 helpers (proj kernel) ----
__device__ __forceinline__ ull ffma2(ull a, ull b, ull c) {
    ull d; asm("fma.rn.f32x2 %0, %1, %2, %3;" : "=l"(d) : "l"(a), "l"(b), "l"(c)); return d;
}
__device__ __forceinline__ float2 unpack2(ull v) {
    float lo, hi; asm("mov.b64 {%0, %1}, %2;" : "=f"(lo), "=f"(hi) : "l"(v));
    return make_float2(lo, hi);
}

__device__ __forceinline__ uint32_t f2u(float x) { return __float_as_uint(x); }

// ---- warp-level tf32 MMA: D(16x8) += A(16x8) * B(8x8) ----
__device__ __forceinline__ void mma_tf32(float c[4], const uint32_t a[4], const uint32_t b[2]) {
    asm volatile(
        "mma.sync.aligned.m16n8k8.row.col.f32.tf32.tf32.f32 "
        "{%0,%1,%2,%3}, {%4,%5,%6,%7}, {%8,%9}, {%0,%1,%2,%3};"
        : "+f"(c[0]), "+f"(c[1]), "+f"(c[2]), "+f"(c[3])
        : "r"(a[0]), "r"(a[1]), "r"(a[2]), "r"(a[3]), "r"(b[0]), "r"(b[1]));
}
// scalar-operand variant (reorders C-frag -> A-frag for free)
__device__ __forceinline__ void mma_tf32s(float c[4], float a0, float a1, float a2, float a3,
                                          float b0, float b1) {
    asm volatile(
        "mma.sync.aligned.m16n8k8.row.col.f32.tf32.tf32.f32 "
        "{%0,%1,%2,%3}, {%4,%5,%6,%7}, {%8,%9}, {%0,%1,%2,%3};"
        : "+f"(c[0]), "+f"(c[1]), "+f"(c[2]), "+f"(c[3])
        : "r"(f2u(a0)), "r"(f2u(a1)), "r"(f2u(a2)), "r"(f2u(a3)),
          "r"(f2u(b0)), "r"(f2u(b1)));
}

__device__ __forceinline__ float ex2f(float x) {
    float r; asm("ex2.approx.f32 %0, %1;" : "=f"(r) : "f"(x)); return r;
}
__device__ __forceinline__ uint32_t smem_u32(const void* p) {
    uint32_t a;
    asm("{ .reg .u64 t; cvta.to.shared.u64 t, %1; cvt.u32.u64 %0, t; }" : "=r"(a) : "l"(p));
    return a;
}

#define CP_ASYNC16(dst_u32, src_ptr) \
    asm volatile("cp.async.ca.shared.global [%0], [%1], 16;" :: "r"(dst_u32), "l"(src_ptr) : "memory")
#define CP_COMMIT() asm volatile("cp.async.commit_group;" ::: "memory")
#define CP_WAIT(n)  asm volatile("cp.async.wait_group %0;" :: "n"(n) : "memory")

// pair-permutation within each 8-block: puts (i, i+4) at adjacent (2i, 2i+1).
__device__ __forceinline__ int perm8(int c) {
    return (c & ~7) | (((c & 3) << 1) | ((c >> 2) & 1));
}

// ============================================================================
// Kernel 1: shared per-head projections.
//   Q: scaled by SCALE_LOG2E, row-major.
//   K: d-columns pair-permuted, row-major.
//   V: row-major (residual) AND transposed into g_Vt via smem (coalesced).
// ============================================================================
__global__ void __launch_bounds__(64) proj_kernel(
    const float* __restrict__ x,
    const float* __restrict__ Wq,
    const float* __restrict__ Wk,
    const float* __restrict__ Wv)
{
    __shared__ __align__(16) float sW[64 * 64];
    __shared__ __align__(16) float sx[64 * 68];

    const int tid = threadIdx.x;
    const int bh  = blockIdx.y;
    const int b   = bh >> 4;
    const int h   = bh & 15;
    const int t0  = blockIdx.x * 64;
    const int t   = t0 + tid;

    const float* xb = x + ((size_t)(b * Tq + t0)) * Eq + h * Dq;
    for (int r = 0; r < 64; ++r)
        sx[r * 68 + tid] = xb[(size_t)r * Eq + tid];

    ull xr[32];
    bool xr_loaded = false;

    #pragma unroll 1
    for (int m = 0; m < 3; ++m) {
        __syncthreads();
        const float* Wsel = (m == 0) ? Wq : ((m == 1) ? Wk : Wv);
        {
            const float4* src = (const float4*)Wsel;
            float4* dst = (float4*)sW;
            #pragma unroll
            for (int i = 0; i < 16; ++i)
                dst[tid + 64 * i] = src[tid + 64 * i];
        }
        __syncthreads();

        if (!xr_loaded) {
            const ulonglong2* row = (const ulonglong2*)(sx + tid * 68);
            #pragma unroll
            for (int i = 0; i < 16; ++i) {
                ulonglong2 v = row[i];
                xr[2 * i] = v.x; xr[2 * i + 1] = v.y;
            }
            xr_loaded = true;
        }

        float* gq = g_Q + ((size_t)bh * Tq + t) * Dq;
        float* gk = g_K + ((size_t)bh * Tq + t) * Dq;
        float* gv = g_V + ((size_t)bh * Tq + t) * Dq;

        #pragma unroll 1
        for (int q0 = 0; q0 < 64; q0 += 4) {
            float acc[4];
            #pragma unroll
            for (int qi = 0; qi < 4; ++qi) {
                const ulonglong2* wr = (const ulonglong2*)(sW + (q0 + qi) * 64);
                ull a0 = 0ull, a1 = 0ull;
                #pragma unroll
                for (int i = 0; i < 16; ++i) {
                    ulonglong2 w = wr[i];
                    a0 = ffma2(xr[2 * i],     w.x, a0);
                    a1 = ffma2(xr[2 * i + 1], w.y, a1);
                }
                float2 f0 = unpack2(a0), f1 = unpack2(a1);
                acc[qi] = (f0.x + f0.y) + (f1.x + f1.y);
            }
            if (m == 0) {
                *(float4*)(gq + q0) = make_float4(acc[0] * SCALE_LOG2E, acc[1] * SCALE_LOG2E,
                                                  acc[2] * SCALE_LOG2E, acc[3] * SCALE_LOG2E);
            } else if (m == 1) {
                #pragma unroll
                for (int qi = 0; qi < 4; ++qi)
                    gk[perm8(q0 + qi)] = acc[qi];
            } else {
                *(float4*)(gv + q0) = make_float4(acc[0], acc[1], acc[2], acc[3]);
                // stash transposed: sx[q][t_local]  (xr already cached in regs)
                #pragma unroll
                for (int qi = 0; qi < 4; ++qi)
                    sx[(q0 + qi) * 68 + tid] = acc[qi];
            }
        }

        if (m == 2) {
            __syncthreads();
            // thread tid owns head-dim row d = tid; write 64 contiguous t's.
            float* dst = g_Vt + (size_t)bh * Dq * Tq + (size_t)tid * Tq + t0;
            const float* srcr = sx + tid * 68;
            #pragma unroll
            for (int j = 0; j < 16; ++j)
                *(float4*)(dst + 4 * j) = *(const float4*)(srcr + 4 * j);
        }
    }
}

// ============================================================================
// Kernel 2: mma.sync tf32 flash attention — pipelined edition.
//   CTA = 256 queries; 8 warps x 32 rows. K-tiles of 64, 4-buffer cp.async
//   ring (one __syncthreads per tile). exp interleaved into the PV loop.
// ============================================================================
#define QBLK 256
#define KBLK 64
#define NT   (Tq / KBLK)              // 32 tiles
#define PKV  72                       // sK / sVt pitch: .64 frags conflict-free
#define FBUF (64 * PKV)               // 4608 floats per matrix tile
#define SMF_TOTAL (8 * FBUF)          // 4 bufs x (K + Vt) = 36864 floats = 147456 B

__global__ void __launch_bounds__(256, 1) attn_kernel(float* __restrict__ out)
{
    extern __shared__ __align__(16) float sm[];

    const int tid  = threadIdx.x;
    const int lane = tid & 31;
    const int wid  = tid >> 5;
    const int lg   = lane >> 2;
    const int lt   = lane & 3;

    const int bh = blockIdx.y;
    const int b  = bh >> 4;
    const int h  = bh & 15;
    const int q0 = blockIdx.x * QBLK;
    const int wq = q0 + wid * 32;

    const uint32_t smb = smem_u32(sm);
    const float* gKb  = g_K  + (size_t)bh * Tq * Dq;
    const float* gVtb = g_Vt + (size_t)bh * Dq * Tq;

    // ---- Q fragments (pre-scaled in proj): 64 regs ----
    uint32_t aQ[2][8][4];
    {
        const float* Qb = g_Q + ((size_t)bh * Tq + wq) * Dq;
        #pragma unroll
        for (int mt = 0; mt < 2; ++mt) {
            const int r0 = mt * 16 + lg;
            #pragma unroll
            for (int k = 0; k < 8; ++k) {
                const int c0 = k * 8 + lt;
                aQ[mt][k][0] = f2u(Qb[(size_t)r0 * Dq + c0]);
                aQ[mt][k][1] = f2u(Qb[(size_t)(r0 + 8) * Dq + c0]);
                aQ[mt][k][2] = f2u(Qb[(size_t)r0 * Dq + c0 + 4]);
                aQ[mt][k][3] = f2u(Qb[(size_t)(r0 + 8) * Dq + c0 + 4]);
            }
        }
    }

    float o[2][8][4];
    #pragma unroll
    for (int mt = 0; mt < 2; ++mt)
        #pragma unroll
        for (int nt = 0; nt < 8; ++nt)
            #pragma unroll
            for (int e = 0; e < 4; ++e) o[mt][nt][e] = 0.f;

    float rs[4] = {0.f, 0.f, 0.f, 0.f};

    // ---- staging helper (cp.async, 8 x 16B per thread) ----
    auto stage = [&](int it, int buf) {
        const uint32_t sKu  = smb + (uint32_t)(buf * 2 * FBUF) * 4u;
        const uint32_t sVtu = sKu + (uint32_t)FBUF * 4u;
        const float* gk = gKb + (size_t)it * KBLK * Dq;
        const int s0 = it * KBLK;
        #pragma unroll
        for (int j = 0; j < 4; ++j) {
            const int f = tid + 256 * j;
            const int r = f >> 4, c4 = f & 15;
            CP_ASYNC16(sKu + (uint32_t)(r * PKV + 4 * c4) * 4u, gk + (size_t)f * 4);
            CP_ASYNC16(sVtu + (uint32_t)(r * PKV + 4 * c4) * 4u,
                       gVtb + (size_t)r * Tq + s0 + 4 * c4);
        }
    };

    stage(0, 0); CP_COMMIT();
    stage(1, 1); CP_COMMIT();

    #pragma unroll 1
    for (int it = 0; it < NT; ++it) {
        // 4-buffer ring: staging (it+2)&3 never collides with a warp still
        // computing tile it-1 in buf (it+3)&3. One barrier per tile.
        if (it + 2 < NT) {
            stage(it + 2, (it + 2) & 3);
            CP_COMMIT();
            CP_WAIT(2);       // group for tile `it` complete (own copies)
        } else if (it + 1 < NT) {
            CP_WAIT(1);
        } else {
            CP_WAIT(0);
        }
        __syncthreads();       // tile `it` visible from all threads

        const float* sK  = sm + (it & 3) * 2 * FBUF;
        const float* sVt = sK + FBUF;

        // ---- QK^T: S(32x64) = Q * K^T, C kept in registers ----
        float c[2][8][4];
        #pragma unroll
        for (int mt = 0; mt < 2; ++mt)
            #pragma unroll
            for (int nt = 0; nt < 8; ++nt)
                #pragma unroll
                for (int e = 0; e < 4; ++e) c[mt][nt][e] = 0.f;

        #pragma unroll
        for (int k = 0; k < 8; ++k) {
            #pragma unroll
            for (int nt = 0; nt < 8; ++nt) {
                const int s = nt * 8 + lg;
                float2 v = *(const float2*)(sK + s * PKV + k * 8 + 2 * lt);
                uint32_t bf[2] = { f2u(v.x), f2u(v.y) };
                mma_tf32(c[0][nt], aQ[0][k], bf);
                mma_tf32(c[1][nt], aQ[1][k], bf);
            }
        }

        // ---- exp (pipelined) + PV. exp(k+1) issues ahead of PV(k) MMAs so
        //      MUFU overlaps the tensor pipe. P C-frag reused as A-frag:
        //      A = {c0, c2, c1, c3}; Vt rows (2lt, 2lt+1) supply B. ----
        #define EXPK(kk) do { \
            _Pragma("unroll") \
            for (int mt = 0; mt < 2; ++mt) { \
                float p0 = ex2f(c[mt][kk][0]); \
                float p1 = ex2f(c[mt][kk][1]); \
                float p2 = ex2f(c[mt][kk][2]); \
                float p3 = ex2f(c[mt][kk][3]); \
                rs[mt * 2 + 0] += p0 + p1; \
                rs[mt * 2 + 1] += p2 + p3; \
                c[mt][kk][0] = p0; c[mt][kk][1] = p1; \
                c[mt][kk][2] = p2; c[mt][kk][3] = p3; \
            } \
        } while (0)

        EXPK(0);
        #pragma unroll
        for (int k = 0; k < 8; ++k) {
            if (k < 7) EXPK(k + 1);
            #pragma unroll
            for (int nt = 0; nt < 8; ++nt) {
                const int d = nt * 8 + lg;
                float2 v = *(const float2*)(sVt + d * PKV + k * 8 + 2 * lt);
                mma_tf32s(o[0][nt], c[0][k][0], c[0][k][2], c[0][k][1], c[0][k][3], v.x, v.y);
                mma_tf32s(o[1][nt], c[1][k][0], c[1][k][2], c[1][k][1], c[1][k][3], v.x, v.y);
            }
        }
        #undef EXPK
    }

    // ---- row sums (reduce over the 4 lanes of each row quad) ----
    float inv[4];
    #pragma unroll
    for (int i = 0; i < 4; ++i) {
        float v = rs[i];
        v += __shfl_xor_sync(0xffffffffu, v, 1);
        v += __shfl_xor_sync(0xffffffffu, v, 2);
        inv[i] = 1.f / v;
    }

    // ---- epilogue: O/l + V residual -> out[b, t, h*64 + d] ----
    #pragma unroll
    for (int mt = 0; mt < 2; ++mt) {
        #pragma unroll
        for (int half = 0; half < 2; ++half) {
            const int t  = wq + mt * 16 + half * 8 + lg;
            const float iv = inv[mt * 2 + half];
            const float2* vr = (const float2*)(g_V + ((size_t)bh * Tq + t) * Dq);
            float2* op = (float2*)(out + ((size_t)(b * Tq + t)) * Eq + h * Dq);
            #pragma unroll
            for (int nt = 0; nt < 8; ++nt) {
                const int idx = nt * 4 + lt;
                float2 v = vr[idx];
                op[idx] = make_float2(o[mt][nt][half * 2 + 0] * iv + v.x,
                                      o[mt][nt][half * 2 + 1] * iv + v.y);
            }
        }
    }
}

// ============================================================================
extern "C" void kernel_launch(void* const* d_in, const int* in_sizes, int n_in,
                              void* d_out, int out_size)
{
    const float* x  = (const float*)d_in[0];
    const float* Wq = (const float*)d_in[1];
    const float* Wk = (const float*)d_in[2];
    const float* Wv = (const float*)d_in[3];
    float* out = (float*)d_out;

    const int smem_bytes = SMF_TOTAL * 4;   // 147456 B
    cudaFuncSetAttribute(attn_kernel, cudaFuncAttributeMaxDynamicSharedMemorySize, smem_bytes);

    dim3 pgrid(Tq / 64, BHq);
    proj_kernel<<<pgrid, 64>>>(x, Wq, Wk, Wv);

    dim3 agrid(Tq / QBLK, BHq);
    attn_kernel<<<agrid, 256, smem_bytes>>>(out);
}

// round 8
// speedup vs baseline: 1.6132x; 1.6132x over previous
#include <cuda_runtime.h>
#include <math.h>
#include <stdint.h>

// Problem constants
#define Bq   4
#define Tq   2048
#define Eq   1024
#define Hq   16
#define Dq   64
#define BHq  (Bq*Hq)

typedef unsigned long long ull;

// Scratch (alloc-free rule: static __device__ arrays).
__device__ uint16_t g_Qb [(size_t)BHq * Tq * Dq];  // bf16, d pair-permuted, pre-scaled
__device__ uint16_t g_Kb [(size_t)BHq * Tq * Dq];  // bf16, d pair-permuted
__device__ float    g_V  [(size_t)BHq * Tq * Dq];  // fp32 row-major (exact residual)
__device__ uint16_t g_Vtb[(size_t)BHq * Dq * Tq];  // bf16, transposed, t pair-permuted

#define SCALE_LOG2E 0.18033688011112042f   // 0.125 * log2(e)

// ---- packed f32x2 helpers (proj kernel) ----
__device__ __forceinline__ ull ffma2(ull a, ull b, ull c) {
    ull d; asm("fma.rn.f32x2 %0, %1, %2, %3;" : "=l"(d) : "l"(a), "l"(b), "l"(c)); return d;
}
__device__ __forceinline__ float2 unpack2(ull v) {
    float lo, hi; asm("mov.b64 {%0, %1}, %2;" : "=f"(lo), "=f"(hi) : "l"(v));
    return make_float2(lo, hi);
}

// ---- bf16 pack: {lo, hi} -> bf16x2 in one u32 ----
__device__ __forceinline__ uint32_t bf2(float lo, float hi) {
    uint32_t r;
    asm("cvt.rn.bf16x2.f32 %0, %1, %2;" : "=r"(r) : "f"(hi), "f"(lo));
    return r;
}

// ---- warp-level bf16 MMA: D(16x8,f32) += A(16x16,bf16) * B(16x8,bf16) ----
__device__ __forceinline__ void mma_bf16(float c[4], const uint32_t a[4],
                                         uint32_t b0, uint32_t b1) {
    asm volatile(
        "mma.sync.aligned.m16n8k16.row.col.f32.bf16.bf16.f32 "
        "{%0,%1,%2,%3}, {%4,%5,%6,%7}, {%8,%9}, {%0,%1,%2,%3};"
        : "+f"(c[0]), "+f"(c[1]), "+f"(c[2]), "+f"(c[3])
        : "r"(a[0]), "r"(a[1]), "r"(a[2]), "r"(a[3]), "r"(b0), "r"(b1));
}

__device__ __forceinline__ float ex2f(float x) {
    float r; asm("ex2.approx.f32 %0, %1;" : "=f"(r) : "f"(x)); return r;
}
__device__ __forceinline__ uint32_t smem_u32(const void* p) {
    uint32_t a;
    asm("{ .reg .u64 t; cvta.to.shared.u64 t, %1; cvt.u32.u64 %0, t; }" : "=r"(a) : "l"(p));
    return a;
}

#define CP_ASYNC16(dst_u32, src_ptr) \
    asm volatile("cp.async.ca.shared.global [%0], [%1], 16;" :: "r"(dst_u32), "l"(src_ptr) : "memory")
#define CP_COMMIT() asm volatile("cp.async.commit_group;" ::: "memory")
#define CP_WAIT(n)  asm volatile("cp.async.wait_group %0;" :: "n"(n) : "memory")

// within each 16-block: actual index d stored at position
//   pos = 4*((d&7)>>1) | 2*((d>>3)&1) | (d&1)
// so stored quad p=4*lt..4*lt+3 holds actual {2lt, 2lt+1, 2lt+8, 2lt+9}
// (exactly the two k-halves one m16n8k16 fragment needs; one LDS.64 feeds both).
__device__ __forceinline__ int pos16(int d) {
    return (d & ~15) | ((((d & 7) >> 1) << 2) | (((d >> 3) & 1) << 1) | (d & 1));
}

// ============================================================================
// Kernel 1: shared per-head projections.
//   Qb: bf16, d pair-permuted, scaled by SCALE_LOG2E.
//   Kb: bf16, d pair-permuted.
//   V : fp32 row-major (exact residual) + Vtb bf16 transposed t-pair-permuted.
// ============================================================================
__global__ void __launch_bounds__(64) proj_kernel(
    const float* __restrict__ x,
    const float* __restrict__ Wq,
    const float* __restrict__ Wk,
    const float* __restrict__ Wv)
{
    __shared__ __align__(16) float sW[64 * 64];
    __shared__ __align__(16) float sx[64 * 68];

    const int tid = threadIdx.x;
    const int bh  = blockIdx.y;
    const int b   = bh >> 4;
    const int h   = bh & 15;
    const int t0  = blockIdx.x * 64;
    const int t   = t0 + tid;

    const float* xb = x + ((size_t)(b * Tq + t0)) * Eq + h * Dq;
    for (int r = 0; r < 64; ++r)
        sx[r * 68 + tid] = xb[(size_t)r * Eq + tid];

    ull xr[32];
    bool xr_loaded = false;

    #pragma unroll 1
    for (int m = 0; m < 3; ++m) {
        __syncthreads();
        const float* Wsel = (m == 0) ? Wq : ((m == 1) ? Wk : Wv);
        {
            const float4* src = (const float4*)Wsel;
            float4* dst = (float4*)sW;
            #pragma unroll
            for (int i = 0; i < 16; ++i)
                dst[tid + 64 * i] = src[tid + 64 * i];
        }
        __syncthreads();

        if (!xr_loaded) {
            const ulonglong2* row = (const ulonglong2*)(sx + tid * 68);
            #pragma unroll
            for (int i = 0; i < 16; ++i) {
                ulonglong2 v = row[i];
                xr[2 * i] = v.x; xr[2 * i + 1] = v.y;
            }
            xr_loaded = true;
        }

        uint16_t* gqb = g_Qb + ((size_t)bh * Tq + t) * Dq;
        uint16_t* gkb = g_Kb + ((size_t)bh * Tq + t) * Dq;
        float*    gv  = g_V  + ((size_t)bh * Tq + t) * Dq;

        #pragma unroll 1
        for (int q0 = 0; q0 < 64; q0 += 4) {
            float acc[4];
            #pragma unroll
            for (int qi = 0; qi < 4; ++qi) {
                const ulonglong2* wr = (const ulonglong2*)(sW + (q0 + qi) * 64);
                ull a0 = 0ull, a1 = 0ull;
                #pragma unroll
                for (int i = 0; i < 16; ++i) {
                    ulonglong2 w = wr[i];
                    a0 = ffma2(xr[2 * i],     w.x, a0);
                    a1 = ffma2(xr[2 * i + 1], w.y, a1);
                }
                float2 f0 = unpack2(a0), f1 = unpack2(a1);
                acc[qi] = (f0.x + f0.y) + (f1.x + f1.y);
            }
            if (m == 0) {
                // q0 % 4 == 0: d pairs (q0,q0+1) and (q0+2,q0+3) land at
                // pos16(q0) and pos16(q0+2), each pair contiguous.
                *(uint32_t*)(gqb + pos16(q0))     = bf2(acc[0] * SCALE_LOG2E, acc[1] * SCALE_LOG2E);
                *(uint32_t*)(gqb + pos16(q0 + 2)) = bf2(acc[2] * SCALE_LOG2E, acc[3] * SCALE_LOG2E);
            } else if (m == 1) {
                *(uint32_t*)(gkb + pos16(q0))     = bf2(acc[0], acc[1]);
                *(uint32_t*)(gkb + pos16(q0 + 2)) = bf2(acc[2], acc[3]);
            } else {
                *(float4*)(gv + q0) = make_float4(acc[0], acc[1], acc[2], acc[3]);
                // stash transposed: sx[q][t_local]
                #pragma unroll
                for (int qi = 0; qi < 4; ++qi)
                    sx[(q0 + qi) * 68 + tid] = acc[qi];
            }
        }

        if (m == 2) {
            __syncthreads();
            // thread tid owns head-dim row d = tid: write 64 t's (bf16,
            // pair-permuted within 16-blocks) coalesced.
            const float* srcr = sx + tid * 68;
            uint16_t* dst = g_Vtb + (size_t)bh * Dq * Tq + (size_t)tid * Tq + t0;
            #pragma unroll
            for (int blk = 0; blk < 4; ++blk) {
                #pragma unroll
                for (int q = 0; q < 4; ++q) {
                    uint32_t wlo = bf2(srcr[blk * 16 + 2 * q],     srcr[blk * 16 + 2 * q + 1]);
                    uint32_t whi = bf2(srcr[blk * 16 + 2 * q + 8], srcr[blk * 16 + 2 * q + 9]);
                    *(uint2*)(dst + blk * 16 + 4 * q) = make_uint2(wlo, whi);
                }
            }
        }
    }
}

// ============================================================================
// Kernel 2: mma.sync bf16 flash attention.
//   CTA = 128 queries; 4 warps x 32 rows; 2 CTAs/SM. K-tiles of 64,
//   4-buffer cp.async ring. P stays in registers (cvt C-frag -> bf16 A-frag).
// ============================================================================
#define QBLK 128
#define KBLK 64
#define NT   (Tq / KBLK)              // 32 tiles
#define PKB  160                      // byte pitch of K/Vt smem rows (conflict-free LDS.64)
#define TILEB (64 * PKB)              // 10240 B per tile
#define SM_BYTES (8 * TILEB)          // 4 bufs x (K + Vt) = 81920 B

__global__ void __launch_bounds__(128, 2) attn_kernel(float* __restrict__ out)
{
    extern __shared__ __align__(16) char smc[];

    const int tid  = threadIdx.x;
    const int lane = tid & 31;
    const int wid  = tid >> 5;
    const int lg   = lane >> 2;
    const int lt   = lane & 3;

    const int bh = blockIdx.y;
    const int b  = bh >> 4;
    const int h  = bh & 15;
    const int q0 = blockIdx.x * QBLK;
    const int wq = q0 + wid * 32;

    const uint32_t smb = smem_u32(smc);
    const uint16_t* gKb  = g_Kb  + (size_t)bh * Tq * Dq;
    const uint16_t* gVtb = g_Vtb + (size_t)bh * Dq * Tq;

    // ---- Q fragments: m16n8k16 A-frags, 2 m-tiles x 4 k-steps x 4 regs ----
    uint32_t aQ[2][4][4];
    {
        const uint16_t* Qb = g_Qb + ((size_t)bh * Tq + wq) * Dq;
        #pragma unroll
        for (int mt = 0; mt < 2; ++mt) {
            #pragma unroll
            for (int kj = 0; kj < 4; ++kj) {
                const uint2 lo = *(const uint2*)(Qb + (size_t)(mt * 16 + lg) * Dq + kj * 16 + 4 * lt);
                const uint2 hi = *(const uint2*)(Qb + (size_t)(mt * 16 + lg + 8) * Dq + kj * 16 + 4 * lt);
                aQ[mt][kj][0] = lo.x;   // rows lg,   k = 2lt,2lt+1
                aQ[mt][kj][1] = hi.x;   // rows lg+8, k = 2lt,2lt+1
                aQ[mt][kj][2] = lo.y;   // rows lg,   k = 2lt+8,2lt+9
                aQ[mt][kj][3] = hi.y;   // rows lg+8, k = 2lt+8,2lt+9
            }
        }
    }

    float o[2][8][4];
    #pragma unroll
    for (int mt = 0; mt < 2; ++mt)
        #pragma unroll
        for (int nt = 0; nt < 8; ++nt)
            #pragma unroll
            for (int e = 0; e < 4; ++e) o[mt][nt][e] = 0.f;

    float rs[4] = {0.f, 0.f, 0.f, 0.f};

    // ---- staging (cp.async, 8 x 16B per thread per tile) ----
    auto stage = [&](int it, int buf) {
        const uint32_t sKu  = smb + (uint32_t)(buf * 2 * TILEB);
        const uint32_t sVtu = sKu + (uint32_t)TILEB;
        const uint16_t* gk = gKb + (size_t)it * KBLK * Dq;
        const int s0 = it * KBLK;
        #pragma unroll
        for (int j = 0; j < 4; ++j) {
            const int f = tid + 128 * j;
            const int r = f >> 3, i = f & 7;
            CP_ASYNC16(sKu + (uint32_t)(r * PKB + 16 * i), gk + (size_t)r * Dq + 8 * i);
            CP_ASYNC16(sVtu + (uint32_t)(r * PKB + 16 * i), gVtb + (size_t)r * Tq + s0 + 8 * i);
        }
    };

    stage(0, 0); CP_COMMIT();
    stage(1, 1); CP_COMMIT();

    #pragma unroll 1
    for (int it = 0; it < NT; ++it) {
        if (it + 2 < NT) {
            stage(it + 2, (it + 2) & 3);
            CP_COMMIT();
            CP_WAIT(2);
        } else if (it + 1 < NT) {
            CP_WAIT(1);
        } else {
            CP_WAIT(0);
        }
        __syncthreads();

        const char* sK  = smc + (it & 3) * 2 * TILEB;
        const char* sVt = sK + TILEB;

        // ---- QK^T: S(32x64) = Q * K^T (bf16, k16 steps) ----
        float c[2][8][4];
        #pragma unroll
        for (int mt = 0; mt < 2; ++mt)
            #pragma unroll
            for (int nt = 0; nt < 8; ++nt)
                #pragma unroll
                for (int e = 0; e < 4; ++e) c[mt][nt][e] = 0.f;

        #pragma unroll
        for (int kj = 0; kj < 4; ++kj) {
            #pragma unroll
            for (int nt = 0; nt < 8; ++nt) {
                const uint2 bv = *(const uint2*)(sK + (nt * 8 + lg) * PKB + 32 * kj + 8 * lt);
                mma_bf16(c[0][nt], aQ[0][kj], bv.x, bv.y);
                mma_bf16(c[1][nt], aQ[1][kj], bv.x, bv.y);
            }
        }

        // ---- exp (pipelined into PV) + PV ----
        #define EXPP(jj) do { \
            _Pragma("unroll") \
            for (int mt = 0; mt < 2; ++mt) { \
                _Pragma("unroll") \
                for (int hh = 0; hh < 2; ++hh) { \
                    float* cc = c[mt][2 * (jj) + hh]; \
                    float p0 = ex2f(cc[0]); \
                    float p1 = ex2f(cc[1]); \
                    float p2 = ex2f(cc[2]); \
                    float p3 = ex2f(cc[3]); \
                    rs[mt * 2 + 0] += p0 + p1; \
                    rs[mt * 2 + 1] += p2 + p3; \
                    cc[0] = p0; cc[1] = p1; cc[2] = p2; cc[3] = p3; \
                } \
            } \
        } while (0)

        EXPP(0);
        #pragma unroll
        for (int j = 0; j < 4; ++j) {
            if (j < 3) EXPP(j + 1);
            // pack P C-frags into bf16 A-frags (s-mapping is identity)
            uint32_t aP0[4], aP1[4];
            aP0[0] = bf2(c[0][2*j][0],   c[0][2*j][1]);
            aP0[1] = bf2(c[0][2*j][2],   c[0][2*j][3]);
            aP0[2] = bf2(c[0][2*j+1][0], c[0][2*j+1][1]);
            aP0[3] = bf2(c[0][2*j+1][2], c[0][2*j+1][3]);
            aP1[0] = bf2(c[1][2*j][0],   c[1][2*j][1]);
            aP1[1] = bf2(c[1][2*j][2],   c[1][2*j][3]);
            aP1[2] = bf2(c[1][2*j+1][0], c[1][2*j+1][1]);
            aP1[3] = bf2(c[1][2*j+1][2], c[1][2*j+1][3]);
            #pragma unroll
            for (int nt = 0; nt < 8; ++nt) {
                const uint2 bv = *(const uint2*)(sVt + (nt * 8 + lg) * PKB + 32 * j + 8 * lt);
                mma_bf16(o[0][nt], aP0, bv.x, bv.y);
                mma_bf16(o[1][nt], aP1, bv.x, bv.y);
            }
        }
        #undef EXPP
    }

    // ---- row sums (reduce over the 4 lanes of each row quad) ----
    float inv[4];
    #pragma unroll
    for (int i = 0; i < 4; ++i) {
        float v = rs[i];
        v += __shfl_xor_sync(0xffffffffu, v, 1);
        v += __shfl_xor_sync(0xffffffffu, v, 2);
        inv[i] = 1.f / v;
    }

    // ---- epilogue: O/l + V residual (exact fp32) -> out[b, t, h*64 + d] ----
    #pragma unroll
    for (int mt = 0; mt < 2; ++mt) {
        #pragma unroll
        for (int half = 0; half < 2; ++half) {
            const int t  = wq + mt * 16 + half * 8 + lg;
            const float iv = inv[mt * 2 + half];
            const float2* vr = (const float2*)(g_V + ((size_t)bh * Tq + t) * Dq);
            float2* op = (float2*)(out + ((size_t)(b * Tq + t)) * Eq + h * Dq);
            #pragma unroll
            for (int nt = 0; nt < 8; ++nt) {
                const int idx = nt * 4 + lt;
                float2 v = vr[idx];
                op[idx] = make_float2(o[mt][nt][half * 2 + 0] * iv + v.x,
                                      o[mt][nt][half * 2 + 1] * iv + v.y);
            }
        }
    }
}

// ============================================================================
extern "C" void kernel_launch(void* const* d_in, const int* in_sizes, int n_in,
                              void* d_out, int out_size)
{
    const float* x  = (const float*)d_in[0];
    const float* Wq = (const float*)d_in[1];
    const float* Wk = (const float*)d_in[2];
    const float* Wv = (const float*)d_in[3];
    float* out = (float*)d_out;

    cudaFuncSetAttribute(attn_kernel, cudaFuncAttributeMaxDynamicSharedMemorySize, SM_BYTES);

    dim3 pgrid(Tq / 64, BHq);
    proj_kernel<<<pgrid, 64>>>(x, Wq, Wk, Wv);

    dim3 agrid(Tq / QBLK, BHq);
    attn_kernel<<<agrid, 128, SM_BYTES>>>(out);
}

// round 9
// speedup vs baseline: 2.1863x; 1.3553x over previous
#include <cuda_runtime.h>
#include <math.h>
#include <stdint.h>

// Problem constants
#define Bq   4
#define Tq   2048
#define Eq   1024
#define Hq   16
#define Dq   64
#define BHq  (Bq*Hq)

// Scratch (alloc-free rule: static __device__ arrays).
__device__ uint16_t g_Qb [(size_t)BHq * Tq * Dq];  // bf16, d pair-permuted, pre-scaled
__device__ uint16_t g_Kb [(size_t)BHq * Tq * Dq];  // bf16, d pair-permuted
__device__ float    g_V  [(size_t)BHq * Tq * Dq];  // fp32 row-major (exact residual)
__device__ uint16_t g_Vtb[(size_t)BHq * Dq * Tq];  // bf16, transposed, t pair-permuted

#define SCALE_LOG2E 0.18033688011112042f   // 0.125 * log2(e)

// ---- bf16 pack: {lo, hi} -> bf16x2 in one u32 ----
__device__ __forceinline__ uint32_t bf2(float lo, float hi) {
    uint32_t r;
    asm("cvt.rn.bf16x2.f32 %0, %1, %2;" : "=r"(r) : "f"(hi), "f"(lo));
    return r;
}

// split a float2 into bf16x2 hi part and bf16x2 residual (lo) part.
__device__ __forceinline__ void split2(float2 p, uint32_t& hi, uint32_t& lo) {
    hi = bf2(p.x, p.y);
    float h0 = __uint_as_float(hi << 16);
    float h1 = __uint_as_float(hi & 0xffff0000u);
    lo = bf2(p.x - h0, p.y - h1);
}

// ---- warp-level bf16 MMA: D(16x8,f32) += A(16x16,bf16) * B(16x8,bf16) ----
__device__ __forceinline__ void mma_bf16(float c[4], const uint32_t a[4],
                                         uint32_t b0, uint32_t b1) {
    asm volatile(
        "mma.sync.aligned.m16n8k16.row.col.f32.bf16.bf16.f32 "
        "{%0,%1,%2,%3}, {%4,%5,%6,%7}, {%8,%9}, {%0,%1,%2,%3};"
        : "+f"(c[0]), "+f"(c[1]), "+f"(c[2]), "+f"(c[3])
        : "r"(a[0]), "r"(a[1]), "r"(a[2]), "r"(a[3]), "r"(b0), "r"(b1));
}

__device__ __forceinline__ float ex2f(float x) {
    float r; asm("ex2.approx.f32 %0, %1;" : "=f"(r) : "f"(x)); return r;
}
__device__ __forceinline__ uint32_t smem_u32(const void* p) {
    uint32_t a;
    asm("{ .reg .u64 t; cvta.to.shared.u64 t, %1; cvt.u32.u64 %0, t; }" : "=r"(a) : "l"(p));
    return a;
}

#define CP_ASYNC16(dst_u32, src_ptr) \
    asm volatile("cp.async.ca.shared.global [%0], [%1], 16;" :: "r"(dst_u32), "l"(src_ptr) : "memory")
#define CP_COMMIT() asm volatile("cp.async.commit_group;" ::: "memory")
#define CP_WAIT(n)  asm volatile("cp.async.wait_group %0;" :: "n"(n) : "memory")

// ============================================================================
// Kernel 1: tensor-core projections with error-compensated bf16.
//   CTA = 128 tokens of one (b,h); 4 warps x 32 rows (2 m-tiles each).
//   For each of Q/K/V: C = xh*Wh + xl*Wh + xh*Wl  (error ~2^-18, near-fp32).
//   Q/K: packed bf16 with the pos16 pair-permutation the attn kernel reads.
//   V:   fp32 row-major (exact-ish residual) + bf16 transpose into g_Vtb.
// ============================================================================
#define PT 66   // smem transpose pitch (floats)

__global__ void __launch_bounds__(128) proj_kernel(
    const float* __restrict__ x,
    const float* __restrict__ Wq,
    const float* __restrict__ Wk,
    const float* __restrict__ Wv)
{
    __shared__ float sVt[128 * PT];   // V tile staged for transpose (33792 B)

    const int tid  = threadIdx.x;
    const int lane = tid & 31;
    const int wid  = tid >> 5;
    const int lg   = lane >> 2;
    const int lt   = lane & 3;

    const int bh = blockIdx.y;
    const int b  = bh >> 4;
    const int h  = bh & 15;
    const int t0 = blockIdx.x * 128;
    const int wq = t0 + wid * 32;

    // ---- load x tile as hi/lo bf16 A-fragments ----
    uint32_t aXh[2][4][4], aXl[2][4][4];
    #pragma unroll
    for (int mt = 0; mt < 2; ++mt) {
        #pragma unroll
        for (int kj = 0; kj < 4; ++kj) {
            const int r0 = wq + mt * 16 + lg;
            const float* p = x + ((size_t)(b * Tq + r0)) * Eq + h * Dq + kj * 16 + 2 * lt;
            float2 lo0 = *(const float2*)(p);
            float2 hi0 = *(const float2*)(p + 8);
            const float* q = p + (size_t)8 * Eq;
            float2 lo1 = *(const float2*)(q);
            float2 hi1 = *(const float2*)(q + 8);
            split2(lo0, aXh[mt][kj][0], aXl[mt][kj][0]);   // row lg,   k=2lt,2lt+1
            split2(lo1, aXh[mt][kj][1], aXl[mt][kj][1]);   // row lg+8
            split2(hi0, aXh[mt][kj][2], aXl[mt][kj][2]);   // row lg,   k=2lt+8,2lt+9
            split2(hi1, aXh[mt][kj][3], aXl[mt][kj][3]);   // row lg+8
        }
    }

    #pragma unroll 1
    for (int m = 0; m < 3; ++m) {
        const float* W = (m == 0) ? Wq : ((m == 1) ? Wk : Wv);

        float c[2][8][4];
        #pragma unroll
        for (int mt = 0; mt < 2; ++mt)
            #pragma unroll
            for (int nt = 0; nt < 8; ++nt)
                #pragma unroll
                for (int e = 0; e < 4; ++e) c[mt][nt][e] = 0.f;

        #pragma unroll
        for (int kj = 0; kj < 4; ++kj) {
            #pragma unroll
            for (int nt = 0; nt < 8; ++nt) {
                const float* wp = W + (size_t)(nt * 8 + lg) * 64 + kj * 16 + 2 * lt;
                uint32_t wh0, wl0, wh1, wl1;
                split2(*(const float2*)(wp),     wh0, wl0);
                split2(*(const float2*)(wp + 8), wh1, wl1);
                #pragma unroll
                for (int mt = 0; mt < 2; ++mt) {
                    mma_bf16(c[mt][nt], aXh[mt][kj], wh0, wh1);   // hi*hi
                    mma_bf16(c[mt][nt], aXl[mt][kj], wh0, wh1);   // lo*hi
                    mma_bf16(c[mt][nt], aXh[mt][kj], wl0, wl1);   // hi*lo
                }
            }
        }

        if (m < 2) {
            // ---- Q/K epilogue: bf16 with pos16 pair-permutation ----
            uint16_t* g = (m == 0 ? g_Qb : g_Kb);
            const float s = (m == 0) ? SCALE_LOG2E : 1.0f;
            #pragma unroll
            for (int mt = 0; mt < 2; ++mt) {
                const int t = wq + mt * 16 + lg;
                uint16_t* r0 = g + ((size_t)bh * Tq + t) * Dq;
                uint16_t* r1 = r0 + (size_t)8 * Dq;
                #pragma unroll
                for (int nt = 0; nt < 8; ++nt) {
                    const int pos = 16 * (nt >> 1) + 4 * lt + 2 * (nt & 1);
                    *(uint32_t*)(r0 + pos) = bf2(c[mt][nt][0] * s, c[mt][nt][1] * s);
                    *(uint32_t*)(r1 + pos) = bf2(c[mt][nt][2] * s, c[mt][nt][3] * s);
                }
            }
        } else {
            // ---- V epilogue: fp32 row-major + smem stage for transpose ----
            #pragma unroll
            for (int mt = 0; mt < 2; ++mt) {
                const int t    = wq + mt * 16 + lg;
                const int tloc = wid * 32 + mt * 16 + lg;
                float* r0 = g_V + ((size_t)bh * Tq + t) * Dq;
                float* r1 = r0 + (size_t)8 * Dq;
                #pragma unroll
                for (int nt = 0; nt < 8; ++nt) {
                    const int col = nt * 8 + 2 * lt;
                    *(float2*)(r0 + col) = make_float2(c[mt][nt][0], c[mt][nt][1]);
                    *(float2*)(r1 + col) = make_float2(c[mt][nt][2], c[mt][nt][3]);
                    *(float2*)(sVt + tloc * PT + col)       = make_float2(c[mt][nt][0], c[mt][nt][1]);
                    *(float2*)(sVt + (tloc + 8) * PT + col) = make_float2(c[mt][nt][2], c[mt][nt][3]);
                }
            }
            __syncthreads();
            // transpose: thread owns head-dim row d, 64 t's (half of the tile)
            const int d    = tid >> 1;
            const int half = tid & 1;
            const float* src = sVt + half * 64 * PT + d;
            uint16_t* dst = g_Vtb + (size_t)bh * Dq * Tq + (size_t)d * Tq + t0 + half * 64;
            #pragma unroll
            for (int blk = 0; blk < 4; ++blk) {
                #pragma unroll
                for (int q = 0; q < 4; ++q) {
                    const float v0 = src[(blk * 16 + 2 * q)     * PT];
                    const float v1 = src[(blk * 16 + 2 * q + 1) * PT];
                    const float v8 = src[(blk * 16 + 2 * q + 8) * PT];
                    const float v9 = src[(blk * 16 + 2 * q + 9) * PT];
                    *(uint2*)(dst + blk * 16 + 4 * q) = make_uint2(bf2(v0, v1), bf2(v8, v9));
                }
            }
        }
    }
}

// ============================================================================
// Kernel 2: mma.sync bf16 flash attention (unchanged from R8).
//   CTA = 128 queries; 4 warps x 32 rows; 2 CTAs/SM. K-tiles of 64,
//   4-buffer cp.async ring. P stays in registers (cvt C-frag -> bf16 A-frag).
// ============================================================================
#define QBLK 128
#define KBLK 64
#define NT   (Tq / KBLK)              // 32 tiles
#define PKB  160                      // byte pitch of K/Vt smem rows
#define TILEB (64 * PKB)              // 10240 B per tile
#define SM_BYTES (8 * TILEB)          // 4 bufs x (K + Vt) = 81920 B

__global__ void __launch_bounds__(128, 2) attn_kernel(float* __restrict__ out)
{
    extern __shared__ __align__(16) char smc[];

    const int tid  = threadIdx.x;
    const int lane = tid & 31;
    const int wid  = tid >> 5;
    const int lg   = lane >> 2;
    const int lt   = lane & 3;

    const int bh = blockIdx.y;
    const int b  = bh >> 4;
    const int h  = bh & 15;
    const int q0 = blockIdx.x * QBLK;
    const int wq = q0 + wid * 32;

    const uint32_t smb = smem_u32(smc);
    const uint16_t* gKb  = g_Kb  + (size_t)bh * Tq * Dq;
    const uint16_t* gVtb = g_Vtb + (size_t)bh * Dq * Tq;

    // ---- Q fragments: m16n8k16 A-frags ----
    uint32_t aQ[2][4][4];
    {
        const uint16_t* Qb = g_Qb + ((size_t)bh * Tq + wq) * Dq;
        #pragma unroll
        for (int mt = 0; mt < 2; ++mt) {
            #pragma unroll
            for (int kj = 0; kj < 4; ++kj) {
                const uint2 lo = *(const uint2*)(Qb + (size_t)(mt * 16 + lg) * Dq + kj * 16 + 4 * lt);
                const uint2 hi = *(const uint2*)(Qb + (size_t)(mt * 16 + lg + 8) * Dq + kj * 16 + 4 * lt);
                aQ[mt][kj][0] = lo.x;
                aQ[mt][kj][1] = hi.x;
                aQ[mt][kj][2] = lo.y;
                aQ[mt][kj][3] = hi.y;
            }
        }
    }

    float o[2][8][4];
    #pragma unroll
    for (int mt = 0; mt < 2; ++mt)
        #pragma unroll
        for (int nt = 0; nt < 8; ++nt)
            #pragma unroll
            for (int e = 0; e < 4; ++e) o[mt][nt][e] = 0.f;

    float rs[4] = {0.f, 0.f, 0.f, 0.f};

    auto stage = [&](int it, int buf) {
        const uint32_t sKu  = smb + (uint32_t)(buf * 2 * TILEB);
        const uint32_t sVtu = sKu + (uint32_t)TILEB;
        const uint16_t* gk = gKb + (size_t)it * KBLK * Dq;
        const int s0 = it * KBLK;
        #pragma unroll
        for (int j = 0; j < 4; ++j) {
            const int f = tid + 128 * j;
            const int r = f >> 3, i = f & 7;
            CP_ASYNC16(sKu + (uint32_t)(r * PKB + 16 * i), gk + (size_t)r * Dq + 8 * i);
            CP_ASYNC16(sVtu + (uint32_t)(r * PKB + 16 * i), gVtb + (size_t)r * Tq + s0 + 8 * i);
        }
    };

    stage(0, 0); CP_COMMIT();
    stage(1, 1); CP_COMMIT();

    #pragma unroll 1
    for (int it = 0; it < NT; ++it) {
        if (it + 2 < NT) {
            stage(it + 2, (it + 2) & 3);
            CP_COMMIT();
            CP_WAIT(2);
        } else if (it + 1 < NT) {
            CP_WAIT(1);
        } else {
            CP_WAIT(0);
        }
        __syncthreads();

        const char* sK  = smc + (it & 3) * 2 * TILEB;
        const char* sVt = sK + TILEB;

        // ---- QK^T ----
        float c[2][8][4];
        #pragma unroll
        for (int mt = 0; mt < 2; ++mt)
            #pragma unroll
            for (int nt = 0; nt < 8; ++nt)
                #pragma unroll
                for (int e = 0; e < 4; ++e) c[mt][nt][e] = 0.f;

        #pragma unroll
        for (int kj = 0; kj < 4; ++kj) {
            #pragma unroll
            for (int nt = 0; nt < 8; ++nt) {
                const uint2 bv = *(const uint2*)(sK + (nt * 8 + lg) * PKB + 32 * kj + 8 * lt);
                mma_bf16(c[0][nt], aQ[0][kj], bv.x, bv.y);
                mma_bf16(c[1][nt], aQ[1][kj], bv.x, bv.y);
            }
        }

        // ---- exp (pipelined into PV) + PV ----
        #define EXPP(jj) do { \
            _Pragma("unroll") \
            for (int mt = 0; mt < 2; ++mt) { \
                _Pragma("unroll") \
                for (int hh = 0; hh < 2; ++hh) { \
                    float* cc = c[mt][2 * (jj) + hh]; \
                    float p0 = ex2f(cc[0]); \
                    float p1 = ex2f(cc[1]); \
                    float p2 = ex2f(cc[2]); \
                    float p3 = ex2f(cc[3]); \
                    rs[mt * 2 + 0] += p0 + p1; \
                    rs[mt * 2 + 1] += p2 + p3; \
                    cc[0] = p0; cc[1] = p1; cc[2] = p2; cc[3] = p3; \
                } \
            } \
        } while (0)

        EXPP(0);
        #pragma unroll
        for (int j = 0; j < 4; ++j) {
            if (j < 3) EXPP(j + 1);
            uint32_t aP0[4], aP1[4];
            aP0[0] = bf2(c[0][2*j][0],   c[0][2*j][1]);
            aP0[1] = bf2(c[0][2*j][2],   c[0][2*j][3]);
            aP0[2] = bf2(c[0][2*j+1][0], c[0][2*j+1][1]);
            aP0[3] = bf2(c[0][2*j+1][2], c[0][2*j+1][3]);
            aP1[0] = bf2(c[1][2*j][0],   c[1][2*j][1]);
            aP1[1] = bf2(c[1][2*j][2],   c[1][2*j][3]);
            aP1[2] = bf2(c[1][2*j+1][0], c[1][2*j+1][1]);
            aP1[3] = bf2(c[1][2*j+1][2], c[1][2*j+1][3]);
            #pragma unroll
            for (int nt = 0; nt < 8; ++nt) {
                const uint2 bv = *(const uint2*)(sVt + (nt * 8 + lg) * PKB + 32 * j + 8 * lt);
                mma_bf16(o[0][nt], aP0, bv.x, bv.y);
                mma_bf16(o[1][nt], aP1, bv.x, bv.y);
            }
        }
        #undef EXPP
    }

    // ---- row sums ----
    float inv[4];
    #pragma unroll
    for (int i = 0; i < 4; ++i) {
        float v = rs[i];
        v += __shfl_xor_sync(0xffffffffu, v, 1);
        v += __shfl_xor_sync(0xffffffffu, v, 2);
        inv[i] = 1.f / v;
    }

    // ---- epilogue: O/l + V residual (fp32) -> out[b, t, h*64 + d] ----
    #pragma unroll
    for (int mt = 0; mt < 2; ++mt) {
        #pragma unroll
        for (int half = 0; half < 2; ++half) {
            const int t  = wq + mt * 16 + half * 8 + lg;
            const float iv = inv[mt * 2 + half];
            const float2* vr = (const float2*)(g_V + ((size_t)bh * Tq + t) * Dq);
            float2* op = (float2*)(out + ((size_t)(b * Tq + t)) * Eq + h * Dq);
            #pragma unroll
            for (int nt = 0; nt < 8; ++nt) {
                const int idx = nt * 4 + lt;
                float2 v = vr[idx];
                op[idx] = make_float2(o[mt][nt][half * 2 + 0] * iv + v.x,
                                      o[mt][nt][half * 2 + 1] * iv + v.y);
            }
        }
    }
}

// ============================================================================
extern "C" void kernel_launch(void* const* d_in, const int* in_sizes, int n_in,
                              void* d_out, int out_size)
{
    const float* x  = (const float*)d_in[0];
    const float* Wq = (const float*)d_in[1];
    const float* Wk = (const float*)d_in[2];
    const float* Wv = (const float*)d_in[3];
    float* out = (float*)d_out;

    cudaFuncSetAttribute(attn_kernel, cudaFuncAttributeMaxDynamicSharedMemorySize, SM_BYTES);

    dim3 pgrid(Tq / 128, BHq);
    proj_kernel<<<pgrid, 128>>>(x, Wq, Wk, Wv);

    dim3 agrid(Tq / QBLK, BHq);
    attn_kernel<<<agrid, 128, SM_BYTES>>>(out);
}